// round 3
// baseline (speedup 1.0000x reference)
#include <cuda_runtime.h>

// Spline2D, two-phase:
//   k1: per-batch separable cubic-B-spline blend -> g_tpl[b][65*65] (17.3 MB, L2-resident)
//   k2: pure streaming writer: 268 MB of fp32 out, zeros outside the 65x65 window,
//       template values (read from L2) inside. No smem, no syncs -> dense store stream.
//
// out[b,i,j] = tpl[b][r][c], r=i-(floor(x)+96), c=j-(floor(y)+96), r,c in [0,64]; else 0.

#define OH 256
#define OW 256
#define CO 72      // coeffs leading dim (64 + 2*4 pad)
#define BATCH_MAX 1024

__device__ float g_tpl[BATCH_MAX * 65 * 65];   // 17.3 MB static scratch

__device__ __forceinline__ void bspline3(float p, float& b0, float& b1, float& b2, float& b3) {
    const float p2 = p * p, p3 = p2 * p, q = 1.0f - p;
    b0 = p3 * (1.0f / 6.0f);
    b1 = -0.5f * p3 + 0.5f * p2 + 0.5f * p + (1.0f / 6.0f);
    b2 =  0.5f * p3 - p2 + (2.0f / 3.0f);
    b3 = q * q * q * (1.0f / 6.0f);
}

// ---- kernel 1: build templates -------------------------------------------
__global__ __launch_bounds__(256) void tpl_kernel(
    const float* __restrict__ coeffs,
    const float* __restrict__ xv,
    const float* __restrict__ yv)
{
    __shared__ float rb[65 * 68];   // rowblend, stride 68

    const int b = blockIdx.x;
    const float x = xv[b], y = yv[b];
    const float sx = x - floorf(x);
    const float sy = y - floorf(y);

    float bx0, bx1, bx2, bx3, by0, by1, by2, by3;
    bspline3(sx, bx0, bx1, bx2, bx3);
    bspline3(sy, by0, by1, by2, by3);

    const int t = threadIdx.x;

    // stage 1: rowblend rb[r][cc] = sum_u bx[u]*coeffs[r+2+u][cc+2]  (65 x 68)
    #pragma unroll 4
    for (int idx = t; idx < 65 * 68; idx += 256) {
        const int r  = idx / 68;
        const int cc = idx - r * 68;
        const float* cp = coeffs + (r + 2) * CO + (cc + 2);
        rb[idx] = bx0 * cp[0] + bx1 * cp[CO] + bx2 * cp[2 * CO] + bx3 * cp[3 * CO];
    }
    __syncthreads();

    // stage 2: column blend, write straight to global template buffer (65 x 65)
    float* tout = g_tpl + b * (65 * 65);
    #pragma unroll 4
    for (int idx = t; idx < 65 * 65; idx += 256) {
        const int r = idx / 65;
        const int c = idx - r * 65;
        const float* rp = rb + r * 68 + c;
        tout[idx] = by0 * rp[0] + by1 * rp[1] + by2 * rp[2] + by3 * rp[3];
    }
}

// ---- kernel 2: stream the 256x256 tiles -----------------------------------
// grid: (4, BATCH) -> each block covers 64 rows of one batch image.
// 256 threads x 16 float4 stores, fully unrolled, no smem, no barriers.
__global__ __launch_bounds__(256) void store_kernel(
    const float* __restrict__ xv,
    const float* __restrict__ yv,
    float* __restrict__ out)
{
    const int b  = blockIdx.y;
    const int i0 = blockIdx.x * 64;              // first output row of this slice

    const float x = __ldg(xv + b), y = __ldg(yv + b);
    const int rbase = (int)floorf(x) + 96;
    const int cbase = (int)floorf(y) + 96;

    const float* __restrict__ tp_b = g_tpl + b * (65 * 65);
    float4* outp = (float4*)(out + (size_t)b * (OH * OW)) + i0 * (OW / 4);

    const int t = threadIdx.x;

    #pragma unroll
    for (int k = 0; k < 16; k++) {
        const int q  = t + k * 256;              // slice-local float4 index (0..4095)
        const int i  = i0 + (q >> 6);            // output row
        const int j0 = (q & 63) << 2;            // starting output column
        float4 v = make_float4(0.f, 0.f, 0.f, 0.f);
        const int r = i - rbase;
        if ((unsigned)r <= 64u) {
            const int c = j0 - cbase;
            const float* tp = tp_b + r * 65;
            if (c >= 0 && c + 3 <= 64) {         // common in-window case
                v.x = tp[c]; v.y = tp[c + 1]; v.z = tp[c + 2]; v.w = tp[c + 3];
            } else {                             // window edge straddles the float4
                if ((unsigned)(c    ) <= 64u) v.x = tp[c];
                if ((unsigned)(c + 1) <= 64u) v.y = tp[c + 1];
                if ((unsigned)(c + 2) <= 64u) v.z = tp[c + 2];
                if ((unsigned)(c + 3) <= 64u) v.w = tp[c + 3];
            }
        }
        __stcs(&outp[q], v);                     // evict-first: keep template L2-hot
    }
}

extern "C" void kernel_launch(void* const* d_in, const int* in_sizes, int n_in,
                              void* d_out, int out_size) {
    const float* coeffs = (const float*)d_in[0];   // (72,72) f32
    const float* x      = (const float*)d_in[1];   // (1024,1,1,1) f32
    const float* y      = (const float*)d_in[2];   // (1024,1,1,1) f32
    float* out          = (float*)d_out;           // (1024,1,256,256) f32

    const int batch = in_sizes[1];                 // 1024

    tpl_kernel<<<batch, 256>>>(coeffs, x, y);
    dim3 grid(4, batch);
    store_kernel<<<grid, 256>>>(x, y, out);
}